// round 1
// baseline (speedup 1.0000x reference)
#include <cuda_runtime.h>
#include <math.h>

// ---------------------------------------------------------------------------
// Problem: B=128, C=320, N=256 (=16x16), GROUPS=5 (64 ch/group), RATIO=8
// Scratch (device globals; no allocation in kernel_launch):
#define SZ 10485760   // 128*320*256
__device__ float g_bands[2][SZ];     // low, mid bands (high = x - low - mid)
__device__ float g_feat[3][SZ];      // per-band conv+GN+residual features
__device__ float g_avg[40960];       // [B][C] channel means
__device__ float g_cw[128 * 960];    // [B][3*C] channel-attention weights
__device__ float g_kappa[2][256];    // circular-conv kernels for low/mid masks

// ---------------------------------------------------------------------------
// Kernel 1: per-(b,c) mean over N=256.  grid (128, 40), block 256 (8 warps)
__global__ void k_avg(const float* __restrict__ x) {
    int b = blockIdx.x;
    int c = blockIdx.y * 8 + (threadIdx.x >> 5);
    int lane = threadIdx.x & 31;
    const float* px = x + ((size_t)b * 320 + c) * 256;
    float s = 0.f;
#pragma unroll
    for (int i = 0; i < 8; i++) s += px[lane + 32 * i];
#pragma unroll
    for (int o = 16; o > 0; o >>= 1) s += __shfl_xor_sync(0xffffffffu, s, o);
    if (lane == 0) g_avg[b * 320 + c] = s * (1.0f / 256.0f);
}

// ---------------------------------------------------------------------------
// Kernel 2: channel attention MLP.  grid 128 (one per b), block 256.
__global__ void k_ca(const float* __restrict__ w1, const float* __restrict__ b1,
                     const float* __restrict__ w2, const float* __restrict__ b2) {
    __shared__ float av[320];
    __shared__ float hs[40];
    int b = blockIdx.x, tid = threadIdx.x;
    for (int e = tid; e < 320; e += 256) av[e] = g_avg[b * 320 + e];
    __syncthreads();
    if (tid < 40) {
        float s = b1[tid];
        for (int c = 0; c < 320; c++) s += av[c] * w1[tid * 320 + c];
        hs[tid] = fmaxf(s, 0.0f);
    }
    __syncthreads();
    for (int o = tid; o < 960; o += 256) {
        float s = b2[o];
#pragma unroll
        for (int k = 0; k < 40; k++) s += hs[k] * w2[o * 40 + k];
        g_cw[b * 960 + o] = 1.0f / (1.0f + expf(-s));
    }
}

// ---------------------------------------------------------------------------
// Kernel 3: build circular-conv kernels kappa[m][a*16+b] from the masks.
// band = Re(ifft2( fft2(x) * M' ))  with M'[u,v] = mask[(u+8)&15][(v+8)&15]
// => band = x (x)circ kappa,  kappa[a,b] = (1/256) sum_{u,v} M'[u,v] cos(2pi(ua+vb)/16)
// Mask fp32 arithmetic replicates JAX: linspace = k*(2/15) + (-1), dist =
// sqrt(x*x + y*y) / fl32(sqrt(2)), all separately rounded (no fma).
__device__ __forceinline__ float jsig(float z) { return 1.0f / (1.0f + expf(-z)); }

__global__ void k_prep(const float* __restrict__ lcp, const float* __restrict__ hcp) {
    __shared__ double ctab[16];
    int t = threadIdx.x;
    if (t < 16) ctab[t] = cos((double)t * 3.14159265358979323846 / 8.0);
    __syncthreads();
    float lc = *lcp, hc = *hcp;
    int a = t >> 4, bb = t & 15;
    float step = __fdiv_rn(2.0f, 15.0f);
    for (int m = 0; m < 2; m++) {
        double acc = 0.0;
        for (int u = 0; u < 16; u++) {
            int s = (u + 8) & 15;
            float yv = __fadd_rn(__fmul_rn((float)s, step), -1.0f);
            for (int v = 0; v < 16; v++) {
                int t2 = (v + 8) & 15;
                float xv = __fadd_rn(__fmul_rn((float)t2, step), -1.0f);
                float d2 = __fadd_rn(__fmul_rn(xv, xv), __fmul_rn(yv, yv));
                float d = __fdiv_rn(__fsqrt_rn(d2), 1.4142135623730951f);
                float mv;
                if (m == 0) {
                    mv = jsig(__fdiv_rn(__fsub_rn(lc, d), 1e-6f));
                } else {
                    float m1 = jsig(__fdiv_rn(__fsub_rn(d, lc), 1e-6f));
                    float m2 = jsig(__fdiv_rn(__fsub_rn(hc, d), 1e-6f));
                    mv = m1 * m2;
                }
                int ph = (u * a + v * bb) & 15;
                acc += (double)mv * ctab[ph];
            }
        }
        g_kappa[m][t] = (float)(acc * (1.0 / 256.0));
    }
}

// ---------------------------------------------------------------------------
// Kernel 4: band GEMM.  out[m][row][p] = sum_q x[row][q] * kappa_m[idx(p,q)]
// rows = B*C = 40960, p,q in [0,256).  Tile: 64 rows x 256 p, K-chunk 32.
__global__ __launch_bounds__(256) void k_band(const float* __restrict__ x) {
    __shared__ float As[64][32];
    __shared__ float Bs[32][256];
    __shared__ float ks[256];
    int m = blockIdx.y;
    int rows0 = blockIdx.x * 64;
    int tid = threadIdx.x;
    ks[tid] = g_kappa[m][tid];
    int tr = tid >> 5, tp = tid & 31;
    float acc[8][8];
#pragma unroll
    for (int i = 0; i < 8; i++)
#pragma unroll
        for (int j = 0; j < 8; j++) acc[i][j] = 0.f;
    int rl = tid >> 2, qo = (tid & 3) * 8;
    for (int kq = 0; kq < 256; kq += 32) {
        __syncthreads();
        const float4* src = (const float4*)(x + (size_t)(rows0 + rl) * 256 + kq + qo);
        float4 a0 = src[0], a1 = src[1];
        *((float4*)&As[rl][qo])     = a0;
        *((float4*)&As[rl][qo + 4]) = a1;
#pragma unroll
        for (int it = 0; it < 32; it++) {
            int q = kq + it, p = tid;
            int aa = ((p >> 4) - (q >> 4)) & 15;
            int bbq = ((p & 15) - (q & 15)) & 15;
            Bs[it][p] = ks[aa * 16 + bbq];
        }
        __syncthreads();
#pragma unroll
        for (int ql = 0; ql < 32; ql++) {
            float av[8], bv[8];
#pragma unroll
            for (int i = 0; i < 8; i++) av[i] = As[tr * 8 + i][ql];
#pragma unroll
            for (int j = 0; j < 8; j++) bv[j] = Bs[ql][tp + 32 * j];
#pragma unroll
            for (int i = 0; i < 8; i++)
#pragma unroll
                for (int j = 0; j < 8; j++) acc[i][j] = fmaf(av[i], bv[j], acc[i][j]);
        }
    }
    float* outp = g_bands[m];
#pragma unroll
    for (int i = 0; i < 8; i++) {
        size_t ro = (size_t)(rows0 + tr * 8 + i) * 256;
#pragma unroll
        for (int j = 0; j < 8; j++) outp[ro + tp + 32 * j] = acc[i][j];
    }
}

// ---------------------------------------------------------------------------
// Kernel 5: 3x3 conv (SAME, zero pad) + bias + GroupNorm + affine + residual.
// grid (5 groups, 128 b, 3 bands), block 256.
// Block tile: 64 out-channels (== one GN group) x 256 pixels of one image.
// Thread tile: 8 co x 8 px (half a pixel row).
__global__ __launch_bounds__(256, 2) void k_conv(
    const float* __restrict__ x,
    const float* __restrict__ wl, const float* __restrict__ bl,
    const float* __restrict__ gl, const float* __restrict__ el,
    const float* __restrict__ wm, const float* __restrict__ bm,
    const float* __restrict__ gm, const float* __restrict__ em,
    const float* __restrict__ wh, const float* __restrict__ bh,
    const float* __restrict__ gh, const float* __restrict__ eh) {
    __shared__ float in_s[8][18][19];   // padded 16x16 + halo, pitch 19 (bank-safe)
    __shared__ float w_s[8][9][64];     // [ci][tap][co] for vectorized co reads
    __shared__ float red_s[256];
    __shared__ float red_q[256];
    __shared__ float stats[2];

    int g = blockIdx.x, b = blockIdx.y, m = blockIdx.z;
    const float *W, *bias, *gam, *bet;
    if (m == 0)      { W = wl; bias = bl; gam = gl; bet = el; }
    else if (m == 1) { W = wm; bias = bm; gam = gm; bet = em; }
    else             { W = wh; bias = bh; gam = gh; bet = eh; }

    int tid = threadIdx.x;
    int tr = tid >> 5;          // co sub-tile: channels tr*8..tr*8+7 of the group
    int tc = tid & 31;
    int r  = tc >> 1;           // pixel row 0..15
    int x0 = (tc & 1) * 8;      // pixel col base 0 or 8

    for (int e = tid; e < 8 * 18 * 19; e += 256) ((float*)in_s)[e] = 0.0f;

    float acc[8][8];
#pragma unroll
    for (int i = 0; i < 8; i++)
#pragma unroll
        for (int j = 0; j < 8; j++) acc[i][j] = 0.f;

    const size_t base_in = (size_t)b * 81920;   // b*320*256
    const float* band0 = g_bands[0];
    const float* band1 = g_bands[1];

    for (int cc = 0; cc < 40; cc++) {           // 40 chunks of 8 input channels
        __syncthreads();
#pragma unroll
        for (int it = 0; it < 8; it++) {        // load 8x256 inputs
            int cl = it, p = tid;
            size_t off = base_in + (size_t)(cc * 8 + cl) * 256 + p;
            float v;
            if (m == 0)      v = band0[off];
            else if (m == 1) v = band1[off];
            else             v = x[off] - band0[off] - band1[off];
            in_s[cl][1 + (p >> 4)][1 + (p & 15)] = v;
        }
#pragma unroll
        for (int it = 0; it < 18; it++) {       // load 64co x 8ci x 9 weights
            int e = tid + 256 * it;
            int co = e / 72, rem = e % 72;
            int cl = rem / 9, k = rem % 9;
            w_s[cl][k][co] = W[(size_t)(g * 64 + co) * 2880 + (cc * 8 + cl) * 9 + k];
        }
        __syncthreads();
#pragma unroll
        for (int cl = 0; cl < 8; cl++) {
            float rin[3][10];
#pragma unroll
            for (int dy = 0; dy < 3; dy++)
#pragma unroll
                for (int dx = 0; dx < 10; dx++)
                    rin[dy][dx] = in_s[cl][r + dy][x0 + dx];
#pragma unroll
            for (int ky = 0; ky < 3; ky++) {
#pragma unroll
                for (int kx = 0; kx < 3; kx++) {
                    const float4* wp = (const float4*)&w_s[cl][ky * 3 + kx][tr * 8];
                    float4 w0 = wp[0], w1 = wp[1];
                    float wv[8] = {w0.x, w0.y, w0.z, w0.w, w1.x, w1.y, w1.z, w1.w};
#pragma unroll
                    for (int ci = 0; ci < 8; ci++)
#pragma unroll
                        for (int px = 0; px < 8; px++)
                            acc[ci][px] = fmaf(wv[ci], rin[ky][px + kx], acc[ci][px]);
                }
            }
        }
    }
    // bias (before GN stats, matching reference)
#pragma unroll
    for (int ci = 0; ci < 8; ci++) {
        float bv = bias[g * 64 + tr * 8 + ci];
#pragma unroll
        for (int px = 0; px < 8; px++) acc[ci][px] += bv;
    }
    // GroupNorm over exactly this block's 64ch x 256px
    float s = 0.f, q = 0.f;
#pragma unroll
    for (int ci = 0; ci < 8; ci++)
#pragma unroll
        for (int px = 0; px < 8; px++) { float v = acc[ci][px]; s += v; q += v * v; }
    red_s[tid] = s; red_q[tid] = q;
    __syncthreads();
    for (int off = 128; off > 0; off >>= 1) {
        if (tid < off) { red_s[tid] += red_s[tid + off]; red_q[tid] += red_q[tid + off]; }
        __syncthreads();
    }
    if (tid == 0) {
        float mu  = red_s[0] * (1.0f / 16384.0f);
        float var = red_q[0] * (1.0f / 16384.0f) - mu * mu;
        stats[0] = mu;
        stats[1] = rsqrtf(var + 1e-5f);
    }
    __syncthreads();
    float mu = stats[0], rs = stats[1];
    float* feat = g_feat[m];
#pragma unroll
    for (int ci = 0; ci < 8; ci++) {
        int c = g * 64 + tr * 8 + ci;
        float ga = gam[c], be = bet[c];
        size_t o = base_in + (size_t)c * 256 + r * 16 + x0;
#pragma unroll
        for (int px = 0; px < 8; px++)
            feat[o + px] = (acc[ci][px] - mu) * rs * ga + be + x[o + px];
    }
}

// ---------------------------------------------------------------------------
// Kernel 6: fused = sum_m cw_m*feat_m; sw = sigmoid(<fused, sa_w> + sa_b);
// out = fused * sw.  grid 128 (b), block 256 (one thread per pixel).
__global__ void k_fuse(const float* __restrict__ saw, const float* __restrict__ sab,
                       float* __restrict__ out) {
    __shared__ float cw_s[960];
    __shared__ float saw_s[320];
    int b = blockIdx.x, p = threadIdx.x;
    for (int e = p; e < 960; e += 256) cw_s[e] = g_cw[b * 960 + e];
    for (int e = p; e < 320; e += 256) saw_s[e] = saw[e];
    __syncthreads();
    size_t base = (size_t)b * 81920 + p;
    float sacc = 0.f;
    for (int c = 0; c < 320; c++) {
        size_t o = base + (size_t)c * 256;
        float f = cw_s[c] * g_feat[0][o] + cw_s[320 + c] * g_feat[1][o]
                + cw_s[640 + c] * g_feat[2][o];
        sacc += f * saw_s[c];
    }
    float sw = 1.0f / (1.0f + expf(-(sacc + sab[0])));
    for (int c = 0; c < 320; c++) {
        size_t o = base + (size_t)c * 256;
        float f = cw_s[c] * g_feat[0][o] + cw_s[320 + c] * g_feat[1][o]
                + cw_s[640 + c] * g_feat[2][o];
        out[o] = f * sw;
    }
}

// ---------------------------------------------------------------------------
extern "C" void kernel_launch(void* const* d_in, const int* in_sizes, int n_in,
                              void* d_out, int out_size) {
    const float* x   = (const float*)d_in[0];
    const float* lc  = (const float*)d_in[1];
    const float* hc  = (const float*)d_in[2];
    const float* w1  = (const float*)d_in[3];
    const float* b1  = (const float*)d_in[4];
    const float* w2  = (const float*)d_in[5];
    const float* b2  = (const float*)d_in[6];
    const float* wl  = (const float*)d_in[7];
    const float* bl  = (const float*)d_in[8];
    const float* gl  = (const float*)d_in[9];
    const float* el  = (const float*)d_in[10];
    const float* wm  = (const float*)d_in[11];
    const float* bm  = (const float*)d_in[12];
    const float* gm  = (const float*)d_in[13];
    const float* em  = (const float*)d_in[14];
    const float* wh  = (const float*)d_in[15];
    const float* bh  = (const float*)d_in[16];
    const float* gh  = (const float*)d_in[17];
    const float* eh  = (const float*)d_in[18];
    const float* saw = (const float*)d_in[19];
    const float* sab = (const float*)d_in[20];
    float* out = (float*)d_out;

    k_avg <<<dim3(128, 40), 256>>>(x);
    k_ca  <<<128, 256>>>(w1, b1, w2, b2);
    k_prep<<<1, 256>>>(lc, hc);
    k_band<<<dim3(640, 2), 256>>>(x);
    k_conv<<<dim3(5, 128, 3), 256>>>(x, wl, bl, gl, el, wm, bm, gm, em, wh, bh, gh, eh);
    k_fuse<<<128, 256>>>(saw, sab, out);
}

// round 2
// speedup vs baseline: 1.0934x; 1.0934x over previous
#include <cuda_runtime.h>
#include <math.h>

// ---------------------------------------------------------------------------
// Problem: B=128, C=320, N=256 (=16x16), GROUPS=5 (64 ch/group), RATIO=8
#define SZ 10485760   // 128*320*256
__device__ float g_bands[2][SZ];     // low, mid bands (high = x - low - mid)
__device__ float g_feat[3][SZ];      // per-band conv+GN+residual features
__device__ float g_avg[40960];       // [B][C] channel means
__device__ float g_cw[128 * 960];    // [B][3*C] channel-attention weights
__device__ float g_kappa[2][256];    // circular-conv kernels for low/mid masks

// ---- packed f32x2 helpers (Blackwell FFMA2 path; ptxas never emits these) --
__device__ __forceinline__ unsigned long long f2pack(float lo, float hi) {
    unsigned long long r;
    asm("mov.b64 %0, {%1, %2};" : "=l"(r) : "f"(lo), "f"(hi));
    return r;
}
__device__ __forceinline__ void f2unpack(unsigned long long v, float& lo, float& hi) {
    asm("mov.b64 {%0, %1}, %2;" : "=f"(lo), "=f"(hi) : "l"(v));
}
__device__ __forceinline__ unsigned long long ffma2(unsigned long long a,
                                                    unsigned long long b,
                                                    unsigned long long c) {
    unsigned long long d;
    asm("fma.rn.f32x2 %0, %1, %2, %3;" : "=l"(d) : "l"(a), "l"(b), "l"(c));
    return d;
}

// ---------------------------------------------------------------------------
// Kernel 1: per-(b,c) mean over N=256.  grid (128, 40), block 256 (8 warps)
__global__ void k_avg(const float* __restrict__ x) {
    int b = blockIdx.x;
    int c = blockIdx.y * 8 + (threadIdx.x >> 5);
    int lane = threadIdx.x & 31;
    const float* px = x + ((size_t)b * 320 + c) * 256;
    float s = 0.f;
#pragma unroll
    for (int i = 0; i < 8; i++) s += px[lane + 32 * i];
#pragma unroll
    for (int o = 16; o > 0; o >>= 1) s += __shfl_xor_sync(0xffffffffu, s, o);
    if (lane == 0) g_avg[b * 320 + c] = s * (1.0f / 256.0f);
}

// ---------------------------------------------------------------------------
// Kernel 2: channel attention MLP.  grid 128 (one per b), block 256.
__global__ void k_ca(const float* __restrict__ w1, const float* __restrict__ b1,
                     const float* __restrict__ w2, const float* __restrict__ b2) {
    __shared__ float av[320];
    __shared__ float hs[40];
    int b = blockIdx.x, tid = threadIdx.x;
    for (int e = tid; e < 320; e += 256) av[e] = g_avg[b * 320 + e];
    __syncthreads();
    if (tid < 40) {
        float s = b1[tid];
        for (int c = 0; c < 320; c++) s += av[c] * w1[tid * 320 + c];
        hs[tid] = fmaxf(s, 0.0f);
    }
    __syncthreads();
    for (int o = tid; o < 960; o += 256) {
        float s = b2[o];
#pragma unroll
        for (int k = 0; k < 40; k++) s += hs[k] * w2[o * 40 + k];
        g_cw[b * 960 + o] = 1.0f / (1.0f + expf(-s));
    }
}

// ---------------------------------------------------------------------------
// Kernel 3: build circular-conv kernels kappa[m] from the masks (JAX-exact fp32).
__device__ __forceinline__ float jsig(float z) { return 1.0f / (1.0f + expf(-z)); }

__global__ void k_prep(const float* __restrict__ lcp, const float* __restrict__ hcp) {
    __shared__ double ctab[16];
    int t = threadIdx.x;
    if (t < 16) ctab[t] = cos((double)t * 3.14159265358979323846 / 8.0);
    __syncthreads();
    float lc = *lcp, hc = *hcp;
    int a = t >> 4, bb = t & 15;
    float step = __fdiv_rn(2.0f, 15.0f);
    for (int m = 0; m < 2; m++) {
        double acc = 0.0;
        for (int u = 0; u < 16; u++) {
            int s = (u + 8) & 15;
            float yv = __fadd_rn(__fmul_rn((float)s, step), -1.0f);
            for (int v = 0; v < 16; v++) {
                int t2 = (v + 8) & 15;
                float xv = __fadd_rn(__fmul_rn((float)t2, step), -1.0f);
                float d2 = __fadd_rn(__fmul_rn(xv, xv), __fmul_rn(yv, yv));
                float d = __fdiv_rn(__fsqrt_rn(d2), 1.4142135623730951f);
                float mv;
                if (m == 0) {
                    mv = jsig(__fdiv_rn(__fsub_rn(lc, d), 1e-6f));
                } else {
                    float m1 = jsig(__fdiv_rn(__fsub_rn(d, lc), 1e-6f));
                    float m2 = jsig(__fdiv_rn(__fsub_rn(hc, d), 1e-6f));
                    mv = m1 * m2;
                }
                int ph = (u * a + v * bb) & 15;
                acc += (double)mv * ctab[ph];
            }
        }
        g_kappa[m][t] = (float)(acc * (1.0 / 256.0));
    }
}

// ---------------------------------------------------------------------------
// Kernel 4: band GEMM with FFMA2.  out[m][row][p] = sum_q x[row][q]*kappa[idx(p,q)]
__global__ __launch_bounds__(256) void k_band(const float* __restrict__ x) {
    __shared__ float As[64][32];
    __shared__ float Bs[32][256];
    __shared__ float ks[256];
    int m = blockIdx.y;
    int rows0 = blockIdx.x * 64;
    int tid = threadIdx.x;
    ks[tid] = g_kappa[m][tid];
    int tr = tid >> 5, tp = tid & 31;
    unsigned long long acc2[4][8];   // row-pairs (i=2pr, 2pr+1) x 8 cols
#pragma unroll
    for (int pr = 0; pr < 4; pr++)
#pragma unroll
        for (int j = 0; j < 8; j++) acc2[pr][j] = 0ull;
    int rl = tid >> 2, qo = (tid & 3) * 8;
    for (int kq = 0; kq < 256; kq += 32) {
        __syncthreads();
        const float4* src = (const float4*)(x + (size_t)(rows0 + rl) * 256 + kq + qo);
        float4 a0 = src[0], a1 = src[1];
        *((float4*)&As[rl][qo])     = a0;
        *((float4*)&As[rl][qo + 4]) = a1;
#pragma unroll
        for (int it = 0; it < 32; it++) {
            int q = kq + it, p = tid;
            int aa = ((p >> 4) - (q >> 4)) & 15;
            int bbq = ((p & 15) - (q & 15)) & 15;
            Bs[it][p] = ks[aa * 16 + bbq];
        }
        __syncthreads();
#pragma unroll
        for (int ql = 0; ql < 32; ql++) {
            unsigned long long av2[4], bv2[8];
#pragma unroll
            for (int pr = 0; pr < 4; pr++)
                av2[pr] = f2pack(As[tr * 8 + 2 * pr][ql], As[tr * 8 + 2 * pr + 1][ql]);
#pragma unroll
            for (int j = 0; j < 8; j++) {
                float bv = Bs[ql][tp + 32 * j];
                bv2[j] = f2pack(bv, bv);
            }
#pragma unroll
            for (int pr = 0; pr < 4; pr++)
#pragma unroll
                for (int j = 0; j < 8; j++)
                    acc2[pr][j] = ffma2(av2[pr], bv2[j], acc2[pr][j]);
        }
    }
    float* outp = g_bands[m];
#pragma unroll
    for (int pr = 0; pr < 4; pr++) {
        size_t r0 = (size_t)(rows0 + tr * 8 + 2 * pr) * 256;
        size_t r1 = r0 + 256;
#pragma unroll
        for (int j = 0; j < 8; j++) {
            float lo, hi;
            f2unpack(acc2[pr][j], lo, hi);
            outp[r0 + tp + 32 * j] = lo;
            outp[r1 + tp + 32 * j] = hi;
        }
    }
}

// ---------------------------------------------------------------------------
// Kernel 5: 3x3 conv + bias + GroupNorm + affine + residual, FFMA2 mainloop.
// grid (5 groups, 128 b, 3 bands), block 256.
// Block tile: 64 out-channels (== one GN group) x 256 pixels of one image.
// Thread tile: 8 co (as 4 packed pairs) x 8 px (half a pixel row).
__global__ __launch_bounds__(256, 2) void k_conv(
    const float* __restrict__ x,
    const float* __restrict__ wl, const float* __restrict__ bl,
    const float* __restrict__ gl, const float* __restrict__ el,
    const float* __restrict__ wm, const float* __restrict__ bm,
    const float* __restrict__ gm, const float* __restrict__ em,
    const float* __restrict__ wh, const float* __restrict__ bh,
    const float* __restrict__ gh, const float* __restrict__ eh) {
    __shared__ float in_s[8][18][19];   // padded 16x16 + halo, pitch 19 (bank-safe)
    __shared__ float w_s[8][9][64];     // [ci][tap][co]; co-pairs contiguous
    __shared__ float red_s[256];
    __shared__ float red_q[256];
    __shared__ float stats[2];

    int g = blockIdx.x, b = blockIdx.y, m = blockIdx.z;
    const float *W, *bias, *gam, *bet;
    if (m == 0)      { W = wl; bias = bl; gam = gl; bet = el; }
    else if (m == 1) { W = wm; bias = bm; gam = gm; bet = em; }
    else             { W = wh; bias = bh; gam = gh; bet = eh; }

    int tid = threadIdx.x;
    int tr = tid >> 5;          // co sub-tile: channels tr*8..tr*8+7 (warp-uniform)
    int tc = tid & 31;
    int r  = tc >> 1;           // pixel row 0..15
    int x0 = (tc & 1) * 8;      // pixel col base 0 or 8

    for (int e = tid; e < 8 * 18 * 19; e += 256) ((float*)in_s)[e] = 0.0f;

    unsigned long long acc2[4][8];   // co-pairs x 8 px
#pragma unroll
    for (int pr = 0; pr < 4; pr++)
#pragma unroll
        for (int px = 0; px < 8; px++) acc2[pr][px] = 0ull;

    const size_t base_in = (size_t)b * 81920;
    const float* band0 = g_bands[0];
    const float* band1 = g_bands[1];

    for (int cc = 0; cc < 40; cc++) {           // 40 chunks of 8 input channels
        __syncthreads();
#pragma unroll
        for (int it = 0; it < 8; it++) {        // load 8x256 inputs
            int cl = it, p = tid;
            size_t off = base_in + (size_t)(cc * 8 + cl) * 256 + p;
            float v;
            if (m == 0)      v = band0[off];
            else if (m == 1) v = band1[off];
            else             v = x[off] - band0[off] - band1[off];
            in_s[cl][1 + (p >> 4)][1 + (p & 15)] = v;
        }
#pragma unroll
        for (int it = 0; it < 18; it++) {       // load 64co x 8ci x 9 weights
            int e = tid + 256 * it;
            int co = e / 72, rem = e % 72;
            int cl = rem / 9, k = rem % 9;
            w_s[cl][k][co] = W[(size_t)(g * 64 + co) * 2880 + (cc * 8 + cl) * 9 + k];
        }
        __syncthreads();
#pragma unroll
        for (int cl = 0; cl < 8; cl++) {
#pragma unroll
            for (int ky = 0; ky < 3; ky++) {
                // one input row for this tap row; broadcast-pack each pixel
                unsigned long long rin2[10];
#pragma unroll
                for (int dx = 0; dx < 10; dx++) {
                    float rv = in_s[cl][r + ky][x0 + dx];
                    rin2[dx] = f2pack(rv, rv);
                }
#pragma unroll
                for (int kx = 0; kx < 3; kx++) {
                    // co-pairs straight out of shared as 64-bit values
                    const ulonglong2* wp =
                        (const ulonglong2*)&w_s[cl][ky * 3 + kx][tr * 8];
                    ulonglong2 wa = wp[0], wb = wp[1];
                    unsigned long long w2[4] = {wa.x, wa.y, wb.x, wb.y};
#pragma unroll
                    for (int pr = 0; pr < 4; pr++)
#pragma unroll
                        for (int px = 0; px < 8; px++)
                            acc2[pr][px] = ffma2(w2[pr], rin2[px + kx], acc2[pr][px]);
                }
            }
        }
    }
    // unpack accumulators, add bias (before GN stats, matching reference)
    float acc[8][8];
#pragma unroll
    for (int pr = 0; pr < 4; pr++)
#pragma unroll
        for (int px = 0; px < 8; px++)
            f2unpack(acc2[pr][px], acc[2 * pr][px], acc[2 * pr + 1][px]);
#pragma unroll
    for (int ci = 0; ci < 8; ci++) {
        float bv = bias[g * 64 + tr * 8 + ci];
#pragma unroll
        for (int px = 0; px < 8; px++) acc[ci][px] += bv;
    }
    // GroupNorm over exactly this block's 64ch x 256px
    float s = 0.f, q = 0.f;
#pragma unroll
    for (int ci = 0; ci < 8; ci++)
#pragma unroll
        for (int px = 0; px < 8; px++) { float v = acc[ci][px]; s += v; q += v * v; }
    red_s[tid] = s; red_q[tid] = q;
    __syncthreads();
    for (int off = 128; off > 0; off >>= 1) {
        if (tid < off) { red_s[tid] += red_s[tid + off]; red_q[tid] += red_q[tid + off]; }
        __syncthreads();
    }
    if (tid == 0) {
        float mu  = red_s[0] * (1.0f / 16384.0f);
        float var = red_q[0] * (1.0f / 16384.0f) - mu * mu;
        stats[0] = mu;
        stats[1] = rsqrtf(var + 1e-5f);
    }
    __syncthreads();
    float mu = stats[0], rs = stats[1];
    float* feat = g_feat[m];
#pragma unroll
    for (int ci = 0; ci < 8; ci++) {
        int c = g * 64 + tr * 8 + ci;
        float ga = gam[c], be = bet[c];
        size_t o = base_in + (size_t)c * 256 + r * 16 + x0;
#pragma unroll
        for (int px = 0; px < 8; px++)
            feat[o + px] = (acc[ci][px] - mu) * rs * ga + be + x[o + px];
    }
}

// ---------------------------------------------------------------------------
// Kernel 6: fused = sum_m cw_m*feat_m; sw = sigmoid(<fused, sa_w> + sa_b);
// out = fused * sw.  grid 128 (b), block 256 (one thread per pixel).
__global__ void k_fuse(const float* __restrict__ saw, const float* __restrict__ sab,
                       float* __restrict__ out) {
    __shared__ float cw_s[960];
    __shared__ float saw_s[320];
    int b = blockIdx.x, p = threadIdx.x;
    for (int e = p; e < 960; e += 256) cw_s[e] = g_cw[b * 960 + e];
    for (int e = p; e < 320; e += 256) saw_s[e] = saw[e];
    __syncthreads();
    size_t base = (size_t)b * 81920 + p;
    float sacc = 0.f;
    for (int c = 0; c < 320; c++) {
        size_t o = base + (size_t)c * 256;
        float f = cw_s[c] * g_feat[0][o] + cw_s[320 + c] * g_feat[1][o]
                + cw_s[640 + c] * g_feat[2][o];
        sacc += f * saw_s[c];
    }
    float sw = 1.0f / (1.0f + expf(-(sacc + sab[0])));
    for (int c = 0; c < 320; c++) {
        size_t o = base + (size_t)c * 256;
        float f = cw_s[c] * g_feat[0][o] + cw_s[320 + c] * g_feat[1][o]
                + cw_s[640 + c] * g_feat[2][o];
        out[o] = f * sw;
    }
}

// ---------------------------------------------------------------------------
extern "C" void kernel_launch(void* const* d_in, const int* in_sizes, int n_in,
                              void* d_out, int out_size) {
    const float* x   = (const float*)d_in[0];
    const float* lc  = (const float*)d_in[1];
    const float* hc  = (const float*)d_in[2];
    const float* w1  = (const float*)d_in[3];
    const float* b1  = (const float*)d_in[4];
    const float* w2  = (const float*)d_in[5];
    const float* b2  = (const float*)d_in[6];
    const float* wl  = (const float*)d_in[7];
    const float* bl  = (const float*)d_in[8];
    const float* gl  = (const float*)d_in[9];
    const float* el  = (const float*)d_in[10];
    const float* wm  = (const float*)d_in[11];
    const float* bm  = (const float*)d_in[12];
    const float* gm  = (const float*)d_in[13];
    const float* em  = (const float*)d_in[14];
    const float* wh  = (const float*)d_in[15];
    const float* bh  = (const float*)d_in[16];
    const float* gh  = (const float*)d_in[17];
    const float* eh  = (const float*)d_in[18];
    const float* saw = (const float*)d_in[19];
    const float* sab = (const float*)d_in[20];
    float* out = (float*)d_out;

    k_avg <<<dim3(128, 40), 256>>>(x);
    k_ca  <<<128, 256>>>(w1, b1, w2, b2);
    k_prep<<<1, 256>>>(lc, hc);
    k_band<<<dim3(640, 2), 256>>>(x);
    k_conv<<<dim3(5, 128, 3), 256>>>(x, wl, bl, gl, el, wm, bm, gm, em, wh, bh, gh, eh);
    k_fuse<<<128, 256>>>(saw, sab, out);
}